// round 5
// baseline (speedup 1.0000x reference)
#include <cuda_runtime.h>

// GraphNetBlock — tf32 tensor-core, 512-thread CTAs (16 warps) for latency hiding.
// probe_idx -> zero_agg -> edge_kernel -> node_kernel
// out layout: node_out [N,128] then edge_out [E,128].

#define THREADS 512
#define TILE_M 64

#define P_A  388   // As pitch (K=384)
#define P_AN 260   // node As pitch (K=256)
#define P_H  260   // H / O pitch
#define P_B1 260   // weight chunk pitch, N=256
#define P_B2 132   // weight chunk pitch, N=128
#define BUFSTRIDE 4160   // 16*260 floats, per chunk buffer

__device__ float g_agg[65536 * 128];
__device__ int g_is64;

#define EDGE_SMEM_F (64 * P_A + 64 * P_H + 2 * BUFSTRIDE)
#define NODE_SMEM_F (64 * P_AN + 64 * P_H + 2 * BUFSTRIDE)

// ---------------- helpers ----------------
__device__ __forceinline__ unsigned f2tf(float x) {
    unsigned u;
    asm("cvt.rna.tf32.f32 %0, %1;" : "=r"(u) : "f"(x));
    return u;
}
__device__ __forceinline__ float f2tf_f(float x) { return __uint_as_float(f2tf(x)); }

__device__ __forceinline__ void cpa16(float* dst, const float* src) {
    unsigned d = (unsigned)__cvta_generic_to_shared(dst);
    asm volatile("cp.async.cg.shared.global [%0], [%1], 16;" :: "r"(d), "l"(src));
}
__device__ __forceinline__ void cpa_commit() { asm volatile("cp.async.commit_group;"); }
__device__ __forceinline__ void cpa_wait1() { asm volatile("cp.async.wait_group 1;"); }
__device__ __forceinline__ void cpa_wait0() { asm volatile("cp.async.wait_group 0;"); }

__device__ __forceinline__ void mma8(float c[4], const unsigned a[4], unsigned b0, unsigned b1) {
    asm volatile(
        "mma.sync.aligned.m16n8k8.row.col.f32.tf32.tf32.f32 "
        "{%0,%1,%2,%3}, {%4,%5,%6,%7}, {%8,%9}, {%0,%1,%2,%3};"
        : "+f"(c[0]), "+f"(c[1]), "+f"(c[2]), "+f"(c[3])
        : "r"(a[0]), "r"(a[1]), "r"(a[2]), "r"(a[3]), "r"(b0), "r"(b1));
}

template<int COLS>
__device__ __forceinline__ void copy_chunk(float* BsBuf, const float* W, int k0, int tid) {
    const int NF4 = 16 * COLS / 4;
    const int P = COLS + 4;
    #pragma unroll
    for (int i = tid; i < NF4; i += THREADS) {
        int r = i / (COLS / 4);
        int c = (i % (COLS / 4)) * 4;
        cpa16(BsBuf + r * P + c, W + (size_t)(k0 + r) * COLS + c);
    }
}

__device__ __forceinline__ long long load_idx(const void* ei, long long i, int is64) {
    if (is64) return ((const long long*)ei)[i];
    return (long long)((const int*)ei)[i];
}
__device__ __forceinline__ long long clamp_idx(long long v, int Nn) {
    if (v < 0) return 0;
    if (v >= Nn) return Nn - 1;
    return v;
}

__global__ void probe_idx_kernel(const void* ei, int E, int Nn) {
    const long long* p64 = (const long long*)ei;
    int ok = 1;
    int n = E < 64 ? E : 64;
    for (int i = 0; i < n; ++i) {
        long long v = p64[i];
        if (v < 0 || v >= Nn) { ok = 0; break; }
    }
    g_is64 = ok;
}

__global__ void zero_agg_kernel(int nf4) {
    int i = blockIdx.x * blockDim.x + threadIdx.x;
    if (i < nf4) ((float4*)g_agg)[i] = make_float4(0.f, 0.f, 0.f, 0.f);
}

// ---------------------------------------------------------------------------
// Edge kernel
// ---------------------------------------------------------------------------
__global__ void __launch_bounds__(THREADS, 1)
edge_kernel(const float* __restrict__ x, const float* __restrict__ ea,
            const void* __restrict__ ei,
            const float* __restrict__ We1, const float* __restrict__ be1,
            const float* __restrict__ We2, const float* __restrict__ be2,
            const float* __restrict__ Wer, const float* __restrict__ ber,
            const float* __restrict__ ge,  const float* __restrict__ bge,
            float* __restrict__ edge_out, int E, int Nn)
{
    extern __shared__ float smem[];
    float* As = smem;                  // [64][P_A]  tf32 EH
    float* Hs = As + 64 * P_A;         // [64][P_H]  tf32 H1, later fp32 O
    float* Bs = Hs + 64 * P_H;         // [2][BUFSTRIDE]

    const int tid  = threadIdx.x;
    const int warp = tid >> 5;
    const int lane = tid & 31;
    const int g    = lane >> 2;
    const int t    = lane & 3;
    const int e0   = blockIdx.x * TILE_M;
    const int is64 = g_is64;

    // ---- gather EH = [ea | x[src] | x[dst]] into As (tf32, row-major) ----
    #pragma unroll
    for (int sweep = 0; sweep < 4; ++sweep) {
        int m = sweep * 16 + warp;
        int ecl = min(e0 + m, E - 1);
        long long s = clamp_idx(load_idx(ei, ecl, is64), Nn);
        long long d = clamp_idx(load_idx(ei, (long long)E + ecl, is64), Nn);
        int k = lane * 4;
        float4 v0 = *(const float4*)(ea + (size_t)ecl * 128 + k);
        float4 v1 = *(const float4*)(x  + (size_t)s   * 128 + k);
        float4 v2 = *(const float4*)(x  + (size_t)d   * 128 + k);
        float* row = As + (size_t)m * P_A;
        *(float4*)(row + k)       = make_float4(f2tf_f(v0.x), f2tf_f(v0.y), f2tf_f(v0.z), f2tf_f(v0.w));
        *(float4*)(row + 128 + k) = make_float4(f2tf_f(v1.x), f2tf_f(v1.y), f2tf_f(v1.z), f2tf_f(v1.w));
        *(float4*)(row + 256 + k) = make_float4(f2tf_f(v2.x), f2tf_f(v2.y), f2tf_f(v2.z), f2tf_f(v2.w));
    }
    __syncthreads();

    const int mw = warp & 1;         // 2 x m32
    const int nw = warp >> 1;        // 8 x n32 (GEMM1) / 8 x n16 (GEMM2)
    const int mb = mw * 32;

    // ================= GEMM1: H = EH @ We1  (64x256, K=384) =================
    {
        const int nb = nw * 32;
        float acc[2][4][4];
        #pragma unroll
        for (int mi = 0; mi < 2; ++mi)
            #pragma unroll
            for (int ni = 0; ni < 4; ++ni)
                #pragma unroll
                for (int q = 0; q < 4; ++q) acc[mi][ni][q] = 0.f;

        copy_chunk<256>(Bs, We1, 0, tid);
        cpa_commit();
        for (int kt = 0; kt < 24; ++kt) {
            if (kt + 1 < 24) {
                copy_chunk<256>(Bs + ((kt + 1) & 1) * BUFSTRIDE, We1, (kt + 1) * 16, tid);
                cpa_commit();
                cpa_wait1();
            } else {
                cpa_wait0();
            }
            __syncthreads();
            const float* B = Bs + (kt & 1) * BUFSTRIDE;
            #pragma unroll
            for (int ks = 0; ks < 2; ++ks) {
                int kk = kt * 16 + ks * 8;
                unsigned a[2][4];
                #pragma unroll
                for (int mi = 0; mi < 2; ++mi) {
                    const unsigned* ap = (const unsigned*)(As + (size_t)(mb + mi * 16 + g) * P_A + kk + t);
                    a[mi][0] = ap[0];
                    a[mi][1] = ap[8 * P_A];
                    a[mi][2] = ap[4];
                    a[mi][3] = ap[8 * P_A + 4];
                }
                #pragma unroll
                for (int ni = 0; ni < 4; ++ni) {
                    int col = nb + ni * 8 + g;
                    unsigned b0 = f2tf(B[(ks * 8 + t) * P_B1 + col]);
                    unsigned b1 = f2tf(B[(ks * 8 + 4 + t) * P_B1 + col]);
                    mma8(acc[0][ni], a[0], b0, b1);
                    mma8(acc[1][ni], a[1], b0, b1);
                }
            }
            __syncthreads();
        }

        // SiLU + bias -> Hs (tf32)
        #pragma unroll
        for (int mi = 0; mi < 2; ++mi) {
            int r0 = mb + mi * 16 + g;
            #pragma unroll
            for (int ni = 0; ni < 4; ++ni) {
                int c0 = nb + ni * 8 + 2 * t;
                float b0 = __ldg(&be1[c0]), b1 = __ldg(&be1[c0 + 1]);
                float v;
                v = acc[mi][ni][0] + b0; Hs[(size_t)r0 * P_H + c0]           = f2tf_f(v / (1.f + __expf(-v)));
                v = acc[mi][ni][1] + b1; Hs[(size_t)r0 * P_H + c0 + 1]       = f2tf_f(v / (1.f + __expf(-v)));
                v = acc[mi][ni][2] + b0; Hs[(size_t)(r0 + 8) * P_H + c0]     = f2tf_f(v / (1.f + __expf(-v)));
                v = acc[mi][ni][3] + b1; Hs[(size_t)(r0 + 8) * P_H + c0 + 1] = f2tf_f(v / (1.f + __expf(-v)));
            }
        }
        __syncthreads();
    }

    // ============ GEMM2: O = H @ We2 + EH @ Wer  (64x128) ============
    float acc2[2][2][4];
    #pragma unroll
    for (int mi = 0; mi < 2; ++mi)
        #pragma unroll
        for (int ni = 0; ni < 2; ++ni)
            #pragma unroll
            for (int q = 0; q < 4; ++q) acc2[mi][ni][q] = 0.f;
    {
        const int nb = nw * 16;
        const int NC = 40;    // 16 chunks (We2 over H) + 24 chunks (Wer over EH)
        copy_chunk<128>(Bs, We2, 0, tid);
        cpa_commit();
        for (int c = 0; c < NC; ++c) {
            if (c + 1 < NC) {
                const float* Wn = (c + 1 < 16) ? We2 : Wer;
                int k0n = (c + 1 < 16) ? (c + 1) * 16 : (c + 1 - 16) * 16;
                copy_chunk<128>(Bs + ((c + 1) & 1) * BUFSTRIDE, Wn, k0n, tid);
                cpa_commit();
                cpa_wait1();
            } else {
                cpa_wait0();
            }
            __syncthreads();
            const float* B = Bs + (c & 1) * BUFSTRIDE;
            const float* Ap = (c < 16) ? Hs : As;
            const int pa    = (c < 16) ? P_H : P_A;
            const int kk0   = (c < 16) ? c * 16 : (c - 16) * 16;
            #pragma unroll
            for (int ks = 0; ks < 2; ++ks) {
                int kk = kk0 + ks * 8;
                unsigned a[2][4];
                #pragma unroll
                for (int mi = 0; mi < 2; ++mi) {
                    const unsigned* ap = (const unsigned*)(Ap + (size_t)(mb + mi * 16 + g) * pa + kk + t);
                    a[mi][0] = ap[0];
                    a[mi][1] = ap[8 * pa];
                    a[mi][2] = ap[4];
                    a[mi][3] = ap[8 * pa + 4];
                }
                #pragma unroll
                for (int ni = 0; ni < 2; ++ni) {
                    int col = nb + ni * 8 + g;
                    unsigned b0 = f2tf(B[(ks * 8 + t) * P_B2 + col]);
                    unsigned b1 = f2tf(B[(ks * 8 + 4 + t) * P_B2 + col]);
                    mma8(acc2[0][ni], a[0], b0, b1);
                    mma8(acc2[1][ni], a[1], b0, b1);
                }
            }
            __syncthreads();
        }
    }

    // store O (fp32) into Hs
    {
        const int nb = nw * 16;
        #pragma unroll
        for (int mi = 0; mi < 2; ++mi) {
            int r0 = mb + mi * 16 + g;
            #pragma unroll
            for (int ni = 0; ni < 2; ++ni) {
                int c0 = nb + ni * 8 + 2 * t;
                Hs[(size_t)r0 * P_H + c0]           = acc2[mi][ni][0];
                Hs[(size_t)r0 * P_H + c0 + 1]       = acc2[mi][ni][1];
                Hs[(size_t)(r0 + 8) * P_H + c0]     = acc2[mi][ni][2];
                Hs[(size_t)(r0 + 8) * P_H + c0 + 1] = acc2[mi][ni][3];
            }
        }
    }
    __syncthreads();

    // ---- epilogue: bias + LayerNorm + write + scatter (4 rows per warp) ----
    int c4 = lane * 4;
    float4 g4 = *(const float4*)&ge[c4];
    float4 q4 = *(const float4*)&bge[c4];
    float bo0 = be2[c4 + 0] + ber[c4 + 0];
    float bo1 = be2[c4 + 1] + ber[c4 + 1];
    float bo2 = be2[c4 + 2] + ber[c4 + 2];
    float bo3 = be2[c4 + 3] + ber[c4 + 3];

    #pragma unroll
    for (int i = 0; i < 4; ++i) {
        int m = warp * 4 + i;
        const float* row = Hs + (size_t)m * P_H;
        float v0 = row[c4 + 0] + bo0, v1 = row[c4 + 1] + bo1;
        float v2 = row[c4 + 2] + bo2, v3 = row[c4 + 3] + bo3;
        float s = v0 + v1 + v2 + v3;
        float sq = v0 * v0 + v1 * v1 + v2 * v2 + v3 * v3;
        #pragma unroll
        for (int o = 16; o > 0; o >>= 1) {
            s  += __shfl_xor_sync(0xffffffffu, s, o);
            sq += __shfl_xor_sync(0xffffffffu, sq, o);
        }
        float mu  = s * (1.f / 128.f);
        float var = sq * (1.f / 128.f) - mu * mu;
        float rstd = rsqrtf(var + 1e-5f);
        int e = e0 + m;
        if (e < E) {
            float4 y;
            y.x = (v0 - mu) * rstd * g4.x + q4.x;
            y.y = (v1 - mu) * rstd * g4.y + q4.y;
            y.z = (v2 - mu) * rstd * g4.z + q4.z;
            y.w = (v3 - mu) * rstd * g4.w + q4.w;
            *(float4*)&edge_out[(size_t)e * 128 + c4] = y;
            long long d = clamp_idx(load_idx(ei, (long long)E + e, is64), Nn);
            float* ap = g_agg + (size_t)d * 128 + c4;
            atomicAdd(ap + 0, y.x);
            atomicAdd(ap + 1, y.y);
            atomicAdd(ap + 2, y.z);
            atomicAdd(ap + 3, y.w);
        }
    }
}

// ---------------------------------------------------------------------------
// Node kernel
// ---------------------------------------------------------------------------
__global__ void __launch_bounds__(THREADS, 1)
node_kernel(const float* __restrict__ x,
            const float* __restrict__ Wn1, const float* __restrict__ bn1,
            const float* __restrict__ Wn2, const float* __restrict__ bn2,
            const float* __restrict__ Wnr, const float* __restrict__ bnr,
            const float* __restrict__ gn,  const float* __restrict__ bgn,
            float* __restrict__ node_out, int Nn)
{
    extern __shared__ float smem[];
    float* As = smem;                   // [64][P_AN]
    float* Hs = As + 64 * P_AN;         // [64][P_H]
    float* Bs = Hs + 64 * P_H;          // [2][BUFSTRIDE]

    const int tid  = threadIdx.x;
    const int warp = tid >> 5;
    const int lane = tid & 31;
    const int g    = lane >> 2;
    const int t    = lane & 3;
    const int n0   = blockIdx.x * TILE_M;

    #pragma unroll
    for (int sweep = 0; sweep < 4; ++sweep) {
        int m = sweep * 16 + warp;
        int nn = min(n0 + m, Nn - 1);
        int k = lane * 4;
        float4 v0 = *(const float4*)(x     + (size_t)nn * 128 + k);
        float4 v1 = *(const float4*)(g_agg + (size_t)nn * 128 + k);
        float* row = As + (size_t)m * P_AN;
        *(float4*)(row + k)       = make_float4(f2tf_f(v0.x), f2tf_f(v0.y), f2tf_f(v0.z), f2tf_f(v0.w));
        *(float4*)(row + 128 + k) = make_float4(f2tf_f(v1.x), f2tf_f(v1.y), f2tf_f(v1.z), f2tf_f(v1.w));
    }
    __syncthreads();

    const int mw = warp & 1;
    const int nw = warp >> 1;
    const int mb = mw * 32;

    // GEMM1: H = NH @ Wn1 (64x256, K=256)
    {
        const int nb = nw * 32;
        float acc[2][4][4];
        #pragma unroll
        for (int mi = 0; mi < 2; ++mi)
            #pragma unroll
            for (int ni = 0; ni < 4; ++ni)
                #pragma unroll
                for (int q = 0; q < 4; ++q) acc[mi][ni][q] = 0.f;

        copy_chunk<256>(Bs, Wn1, 0, tid);
        cpa_commit();
        for (int kt = 0; kt < 16; ++kt) {
            if (kt + 1 < 16) {
                copy_chunk<256>(Bs + ((kt + 1) & 1) * BUFSTRIDE, Wn1, (kt + 1) * 16, tid);
                cpa_commit();
                cpa_wait1();
            } else {
                cpa_wait0();
            }
            __syncthreads();
            const float* B = Bs + (kt & 1) * BUFSTRIDE;
            #pragma unroll
            for (int ks = 0; ks < 2; ++ks) {
                int kk = kt * 16 + ks * 8;
                unsigned a[2][4];
                #pragma unroll
                for (int mi = 0; mi < 2; ++mi) {
                    const unsigned* ap = (const unsigned*)(As + (size_t)(mb + mi * 16 + g) * P_AN + kk + t);
                    a[mi][0] = ap[0];
                    a[mi][1] = ap[8 * P_AN];
                    a[mi][2] = ap[4];
                    a[mi][3] = ap[8 * P_AN + 4];
                }
                #pragma unroll
                for (int ni = 0; ni < 4; ++ni) {
                    int col = nb + ni * 8 + g;
                    unsigned b0 = f2tf(B[(ks * 8 + t) * P_B1 + col]);
                    unsigned b1 = f2tf(B[(ks * 8 + 4 + t) * P_B1 + col]);
                    mma8(acc[0][ni], a[0], b0, b1);
                    mma8(acc[1][ni], a[1], b0, b1);
                }
            }
            __syncthreads();
        }

        #pragma unroll
        for (int mi = 0; mi < 2; ++mi) {
            int r0 = mb + mi * 16 + g;
            #pragma unroll
            for (int ni = 0; ni < 4; ++ni) {
                int c0 = nb + ni * 8 + 2 * t;
                float b0 = __ldg(&bn1[c0]), b1 = __ldg(&bn1[c0 + 1]);
                float v;
                v = acc[mi][ni][0] + b0; Hs[(size_t)r0 * P_H + c0]           = f2tf_f(v / (1.f + __expf(-v)));
                v = acc[mi][ni][1] + b1; Hs[(size_t)r0 * P_H + c0 + 1]       = f2tf_f(v / (1.f + __expf(-v)));
                v = acc[mi][ni][2] + b0; Hs[(size_t)(r0 + 8) * P_H + c0]     = f2tf_f(v / (1.f + __expf(-v)));
                v = acc[mi][ni][3] + b1; Hs[(size_t)(r0 + 8) * P_H + c0 + 1] = f2tf_f(v / (1.f + __expf(-v)));
            }
        }
        __syncthreads();
    }

    // GEMM2: O = H @ Wn2 + NH @ Wnr (64x128, K=256 each)
    float acc2[2][2][4];
    #pragma unroll
    for (int mi = 0; mi < 2; ++mi)
        #pragma unroll
        for (int ni = 0; ni < 2; ++ni)
            #pragma unroll
            for (int q = 0; q < 4; ++q) acc2[mi][ni][q] = 0.f;
    {
        const int nb = nw * 16;
        const int NC = 32;   // 16 (Wn2 over H) + 16 (Wnr over NH)
        copy_chunk<128>(Bs, Wn2, 0, tid);
        cpa_commit();
        for (int c = 0; c < NC; ++c) {
            if (c + 1 < NC) {
                const float* Wnx = (c + 1 < 16) ? Wn2 : Wnr;
                int k0n = (c + 1 < 16) ? (c + 1) * 16 : (c + 1 - 16) * 16;
                copy_chunk<128>(Bs + ((c + 1) & 1) * BUFSTRIDE, Wnx, k0n, tid);
                cpa_commit();
                cpa_wait1();
            } else {
                cpa_wait0();
            }
            __syncthreads();
            const float* B = Bs + (c & 1) * BUFSTRIDE;
            const float* Ap = (c < 16) ? Hs : As;
            const int pa    = (c < 16) ? P_H : P_AN;
            const int kk0   = (c < 16) ? c * 16 : (c - 16) * 16;
            #pragma unroll
            for (int ks = 0; ks < 2; ++ks) {
                int kk = kk0 + ks * 8;
                unsigned a[2][4];
                #pragma unroll
                for (int mi = 0; mi < 2; ++mi) {
                    const unsigned* ap = (const unsigned*)(Ap + (size_t)(mb + mi * 16 + g) * pa + kk + t);
                    a[mi][0] = ap[0];
                    a[mi][1] = ap[8 * pa];
                    a[mi][2] = ap[4];
                    a[mi][3] = ap[8 * pa + 4];
                }
                #pragma unroll
                for (int ni = 0; ni < 2; ++ni) {
                    int col = nb + ni * 8 + g;
                    unsigned b0 = f2tf(B[(ks * 8 + t) * P_B2 + col]);
                    unsigned b1 = f2tf(B[(ks * 8 + 4 + t) * P_B2 + col]);
                    mma8(acc2[0][ni], a[0], b0, b1);
                    mma8(acc2[1][ni], a[1], b0, b1);
                }
            }
            __syncthreads();
        }
    }

    {
        const int nb = nw * 16;
        #pragma unroll
        for (int mi = 0; mi < 2; ++mi) {
            int r0 = mb + mi * 16 + g;
            #pragma unroll
            for (int ni = 0; ni < 2; ++ni) {
                int c0 = nb + ni * 8 + 2 * t;
                Hs[(size_t)r0 * P_H + c0]           = acc2[mi][ni][0];
                Hs[(size_t)r0 * P_H + c0 + 1]       = acc2[mi][ni][1];
                Hs[(size_t)(r0 + 8) * P_H + c0]     = acc2[mi][ni][2];
                Hs[(size_t)(r0 + 8) * P_H + c0 + 1] = acc2[mi][ni][3];
            }
        }
    }
    __syncthreads();

    int c4 = lane * 4;
    float4 g4 = *(const float4*)&gn[c4];
    float4 q4 = *(const float4*)&bgn[c4];
    float bo0 = bn2[c4 + 0] + bnr[c4 + 0];
    float bo1 = bn2[c4 + 1] + bnr[c4 + 1];
    float bo2 = bn2[c4 + 2] + bnr[c4 + 2];
    float bo3 = bn2[c4 + 3] + bnr[c4 + 3];

    #pragma unroll
    for (int i = 0; i < 4; ++i) {
        int m = warp * 4 + i;
        const float* row = Hs + (size_t)m * P_H;
        float v0 = row[c4 + 0] + bo0, v1 = row[c4 + 1] + bo1;
        float v2 = row[c4 + 2] + bo2, v3 = row[c4 + 3] + bo3;
        float s = v0 + v1 + v2 + v3;
        float sq = v0 * v0 + v1 * v1 + v2 * v2 + v3 * v3;
        #pragma unroll
        for (int o = 16; o > 0; o >>= 1) {
            s  += __shfl_xor_sync(0xffffffffu, s, o);
            sq += __shfl_xor_sync(0xffffffffu, sq, o);
        }
        float mu  = s * (1.f / 128.f);
        float var = sq * (1.f / 128.f) - mu * mu;
        float rstd = rsqrtf(var + 1e-5f);
        int n = n0 + m;
        if (n < Nn) {
            float4 y;
            y.x = (v0 - mu) * rstd * g4.x + q4.x;
            y.y = (v1 - mu) * rstd * g4.y + q4.y;
            y.z = (v2 - mu) * rstd * g4.z + q4.z;
            y.w = (v3 - mu) * rstd * g4.w + q4.w;
            *(float4*)&node_out[(size_t)n * 128 + c4] = y;
        }
    }
}

extern "C" void kernel_launch(void* const* d_in, const int* in_sizes, int n_in,
                              void* d_out, int out_size) {
    const float* x   = (const float*)d_in[0];
    const float* ea  = (const float*)d_in[1];
    const void*  ei  = d_in[2];
    const float* We1 = (const float*)d_in[3];
    const float* be1 = (const float*)d_in[4];
    const float* We2 = (const float*)d_in[5];
    const float* be2 = (const float*)d_in[6];
    const float* Wer = (const float*)d_in[7];
    const float* ber = (const float*)d_in[8];
    const float* ge  = (const float*)d_in[9];
    const float* bge = (const float*)d_in[10];
    const float* Wn1 = (const float*)d_in[11];
    const float* bn1 = (const float*)d_in[12];
    const float* Wn2 = (const float*)d_in[13];
    const float* bn2 = (const float*)d_in[14];
    const float* Wnr = (const float*)d_in[15];
    const float* bnr = (const float*)d_in[16];
    const float* gn  = (const float*)d_in[17];
    const float* bgn = (const float*)d_in[18];

    int Nn = in_sizes[0] / 128;
    int E  = in_sizes[1] / 128;

    float* out      = (float*)d_out;
    float* node_out = out;
    float* edge_out = out + (size_t)Nn * 128;

    cudaFuncSetAttribute(edge_kernel, cudaFuncAttributeMaxDynamicSharedMemorySize,
                         EDGE_SMEM_F * 4);
    cudaFuncSetAttribute(node_kernel, cudaFuncAttributeMaxDynamicSharedMemorySize,
                         NODE_SMEM_F * 4);

    probe_idx_kernel<<<1, 1>>>(ei, E, Nn);

    int nf4 = Nn * 32;
    zero_agg_kernel<<<(nf4 + 255) / 256, 256>>>(nf4);

    edge_kernel<<<(E + TILE_M - 1) / TILE_M, THREADS, EDGE_SMEM_F * 4>>>(
        x, ea, ei, We1, be1, We2, be2, Wer, ber, ge, bge, edge_out, E, Nn);

    node_kernel<<<(Nn + TILE_M - 1) / TILE_M, THREADS, NODE_SMEM_F * 4>>>(
        x, Wn1, bn1, Wn2, bn2, Wnr, bnr, gn, bgn, node_out, Nn);
}

// round 7
// speedup vs baseline: 1.2100x; 1.2100x over previous
#include <cuda_runtime.h>

// GraphNetBlock — tf32 tensor-core v3: preconverted tf32 weights, conflict-free
// B pitches, 256-thread CTAs (m32n64 / m32n32 warp tiles).
// cvt_weights + probe_idx + zero_agg -> edge_kernel -> node_kernel
// out layout: node_out [N,128] then edge_out [E,128].

#define THREADS 256
#define TILE_M 64

#define P_A  388   // As pitch (K=384), == 4 mod 32: A-frag conflict-free
#define P_AN 260   // node As pitch (K=256)
#define P_H  260   // H / O pitch (A-operand of GEMM2)
#define P_B1 264   // weight chunk pitch, N=256; == 8 mod 32: B-frag conflict-free
#define P_B2 136   // weight chunk pitch, N=128; == 8 mod 32
#define BUFSTRIDE 4224   // 16*264 floats, per chunk buffer

__device__ float g_agg[65536 * 128];
__device__ int g_is64;

// preconverted tf32 weights
#define OFF_We1 0
#define OFF_We2 98304
#define OFF_Wer 131072
#define OFF_Wn1 180224
#define OFF_Wn2 245760
#define OFF_Wnr 278528
#define W_TOTAL 311296
__device__ float g_wtf[W_TOTAL];

#define EDGE_SMEM_F (64 * P_A + 64 * P_H + 2 * BUFSTRIDE)   // 49920 fl = 199.7KB
#define NODE_SMEM_F (64 * P_AN + 64 * P_H + 2 * BUFSTRIDE)  // 41728 fl = 166.9KB

// ---------------- helpers ----------------
__device__ __forceinline__ unsigned f2tf(float x) {
    unsigned u;
    asm("cvt.rna.tf32.f32 %0, %1;" : "=r"(u) : "f"(x));
    return u;
}
__device__ __forceinline__ float f2tf_f(float x) { return __uint_as_float(f2tf(x)); }

__device__ __forceinline__ void cpa16(float* dst, const float* src) {
    unsigned d = (unsigned)__cvta_generic_to_shared(dst);
    asm volatile("cp.async.cg.shared.global [%0], [%1], 16;" :: "r"(d), "l"(src));
}
__device__ __forceinline__ void cpa_commit() { asm volatile("cp.async.commit_group;"); }
__device__ __forceinline__ void cpa_wait1() { asm volatile("cp.async.wait_group 1;"); }
__device__ __forceinline__ void cpa_wait0() { asm volatile("cp.async.wait_group 0;"); }

__device__ __forceinline__ void mma8(float c[4], const unsigned a[4], unsigned b0, unsigned b1) {
    asm volatile(
        "mma.sync.aligned.m16n8k8.row.col.f32.tf32.tf32.f32 "
        "{%0,%1,%2,%3}, {%4,%5,%6,%7}, {%8,%9}, {%0,%1,%2,%3};"
        : "+f"(c[0]), "+f"(c[1]), "+f"(c[2]), "+f"(c[3])
        : "r"(a[0]), "r"(a[1]), "r"(a[2]), "r"(a[3]), "r"(b0), "r"(b1));
}

// copy one [16 x COLS] tf32 weight chunk gmem -> smem (pitch P) via cp.async
template<int COLS, int P>
__device__ __forceinline__ void copy_chunk(float* BsBuf, const float* W, int k0, int tid) {
    const int NF4 = 16 * COLS / 4;
    #pragma unroll
    for (int i = tid; i < NF4; i += THREADS) {
        int r = i / (COLS / 4);
        int c = (i % (COLS / 4)) * 4;
        cpa16(BsBuf + r * P + c, W + (size_t)(k0 + r) * COLS + c);
    }
}

__device__ __forceinline__ long long load_idx(const void* ei, long long i, int is64) {
    if (is64) return ((const long long*)ei)[i];
    return (long long)((const int*)ei)[i];
}
__device__ __forceinline__ long long clamp_idx(long long v, int Nn) {
    if (v < 0) return 0;
    if (v >= Nn) return Nn - 1;
    return v;
}

__global__ void probe_idx_kernel(const void* ei, int E, int Nn) {
    int n = E < 64 ? E : 64;
    int bad = 0;
    if (threadIdx.x < n) {
        long long v = ((const long long*)ei)[threadIdx.x];
        bad = (v < 0 || v >= Nn);
    }
    unsigned anybad = __ballot_sync(0xffffffffu, bad);
    __shared__ unsigned s[2];
    if ((threadIdx.x & 31) == 0) s[threadIdx.x >> 5] = anybad;
    __syncthreads();
    if (threadIdx.x == 0) g_is64 = (s[0] | s[1]) ? 0 : 1;
}

__global__ void zero_agg_kernel(int nf4) {
    int i = blockIdx.x * blockDim.x + threadIdx.x;
    if (i < nf4) ((float4*)g_agg)[i] = make_float4(0.f, 0.f, 0.f, 0.f);
}

// convert all weights to tf32 into g_wtf (one float4 per thread slot)
__global__ void cvt_weights_kernel(const float* We1, const float* We2, const float* Wer,
                                   const float* Wn1, const float* Wn2, const float* Wnr) {
    int i4 = blockIdx.x * blockDim.x + threadIdx.x;
    int i = i4 * 4;
    if (i >= W_TOTAL) return;
    const float* src;
    int off;
    if      (i < OFF_We2) { src = We1; off = OFF_We1; }
    else if (i < OFF_Wer) { src = We2; off = OFF_We2; }
    else if (i < OFF_Wn1) { src = Wer; off = OFF_Wer; }
    else if (i < OFF_Wn2) { src = Wn1; off = OFF_Wn1; }
    else if (i < OFF_Wnr) { src = Wn2; off = OFF_Wn2; }
    else                  { src = Wnr; off = OFF_Wnr; }
    float4 v = *(const float4*)(src + (i - off));
    *(float4*)(g_wtf + i) = make_float4(f2tf_f(v.x), f2tf_f(v.y), f2tf_f(v.z), f2tf_f(v.w));
}

// ---------------------------------------------------------------------------
// Edge kernel
// ---------------------------------------------------------------------------
__global__ void __launch_bounds__(THREADS, 1)
edge_kernel(const float* __restrict__ x, const float* __restrict__ ea,
            const void* __restrict__ ei,
            const float* __restrict__ be1, const float* __restrict__ be2,
            const float* __restrict__ ber,
            const float* __restrict__ ge,  const float* __restrict__ bge,
            float* __restrict__ edge_out, int E, int Nn)
{
    extern __shared__ float smem[];
    float* As = smem;                  // [64][P_A]  tf32 EH
    float* Hs = As + 64 * P_A;         // [64][P_H]  tf32 H1, later fp32 O
    float* Bs = Hs + 64 * P_H;         // [2][BUFSTRIDE]

    const float* We1 = g_wtf + OFF_We1;
    const float* We2 = g_wtf + OFF_We2;
    const float* Wer = g_wtf + OFF_Wer;

    const int tid  = threadIdx.x;
    const int warp = tid >> 5;
    const int lane = tid & 31;
    const int g    = lane >> 2;
    const int t    = lane & 3;
    const int e0   = blockIdx.x * TILE_M;
    const int is64 = g_is64;

    // ---- gather EH = [ea | x[src] | x[dst]] into As (tf32, row-major) ----
    #pragma unroll
    for (int sweep = 0; sweep < 8; ++sweep) {
        int m = sweep * 8 + warp;
        int ecl = min(e0 + m, E - 1);
        long long s = clamp_idx(load_idx(ei, ecl, is64), Nn);
        long long d = clamp_idx(load_idx(ei, (long long)E + ecl, is64), Nn);
        int k = lane * 4;
        float4 v0 = *(const float4*)(ea + (size_t)ecl * 128 + k);
        float4 v1 = *(const float4*)(x  + (size_t)s   * 128 + k);
        float4 v2 = *(const float4*)(x  + (size_t)d   * 128 + k);
        float* row = As + (size_t)m * P_A;
        *(float4*)(row + k)       = make_float4(f2tf_f(v0.x), f2tf_f(v0.y), f2tf_f(v0.z), f2tf_f(v0.w));
        *(float4*)(row + 128 + k) = make_float4(f2tf_f(v1.x), f2tf_f(v1.y), f2tf_f(v1.z), f2tf_f(v1.w));
        *(float4*)(row + 256 + k) = make_float4(f2tf_f(v2.x), f2tf_f(v2.y), f2tf_f(v2.z), f2tf_f(v2.w));
    }
    __syncthreads();

    const int mw = warp & 1;         // 2 x m32
    const int nw = warp >> 1;        // 4 x n64 (GEMM1) / 4 x n32 (GEMM2)
    const int mb = mw * 32;

    // ================= GEMM1: H = EH @ We1  (64x256, K=384) =================
    {
        const int nb = nw * 64;
        float acc[2][8][4];
        #pragma unroll
        for (int mi = 0; mi < 2; ++mi)
            #pragma unroll
            for (int ni = 0; ni < 8; ++ni)
                #pragma unroll
                for (int q = 0; q < 4; ++q) acc[mi][ni][q] = 0.f;

        copy_chunk<256, P_B1>(Bs, We1, 0, tid);
        cpa_commit();
        for (int kt = 0; kt < 24; ++kt) {
            if (kt + 1 < 24) {
                copy_chunk<256, P_B1>(Bs + ((kt + 1) & 1) * BUFSTRIDE, We1, (kt + 1) * 16, tid);
                cpa_commit();
                cpa_wait1();
            } else {
                cpa_wait0();
            }
            __syncthreads();
            const unsigned* B = (const unsigned*)(Bs + (kt & 1) * BUFSTRIDE);
            #pragma unroll
            for (int ks = 0; ks < 2; ++ks) {
                int kk = kt * 16 + ks * 8;
                unsigned a[2][4];
                #pragma unroll
                for (int mi = 0; mi < 2; ++mi) {
                    const unsigned* ap = (const unsigned*)(As + (size_t)(mb + mi * 16 + g) * P_A + kk + t);
                    a[mi][0] = ap[0];
                    a[mi][1] = ap[8 * P_A];
                    a[mi][2] = ap[4];
                    a[mi][3] = ap[8 * P_A + 4];
                }
                #pragma unroll
                for (int ni = 0; ni < 8; ++ni) {
                    int col = nb + ni * 8 + g;
                    unsigned b0 = B[(ks * 8 + t) * P_B1 + col];
                    unsigned b1 = B[(ks * 8 + 4 + t) * P_B1 + col];
                    mma8(acc[0][ni], a[0], b0, b1);
                    mma8(acc[1][ni], a[1], b0, b1);
                }
            }
            __syncthreads();
        }

        // SiLU + bias -> Hs (tf32)
        #pragma unroll
        for (int mi = 0; mi < 2; ++mi) {
            int r0 = mb + mi * 16 + g;
            #pragma unroll
            for (int ni = 0; ni < 8; ++ni) {
                int c0 = nb + ni * 8 + 2 * t;
                float b0 = __ldg(&be1[c0]), b1 = __ldg(&be1[c0 + 1]);
                float v;
                v = acc[mi][ni][0] + b0; Hs[(size_t)r0 * P_H + c0]           = f2tf_f(v / (1.f + __expf(-v)));
                v = acc[mi][ni][1] + b1; Hs[(size_t)r0 * P_H + c0 + 1]       = f2tf_f(v / (1.f + __expf(-v)));
                v = acc[mi][ni][2] + b0; Hs[(size_t)(r0 + 8) * P_H + c0]     = f2tf_f(v / (1.f + __expf(-v)));
                v = acc[mi][ni][3] + b1; Hs[(size_t)(r0 + 8) * P_H + c0 + 1] = f2tf_f(v / (1.f + __expf(-v)));
            }
        }
        __syncthreads();
    }

    // ============ GEMM2: O = H @ We2 + EH @ Wer  (64x128) ============
    float acc2[2][4][4];
    #pragma unroll
    for (int mi = 0; mi < 2; ++mi)
        #pragma unroll
        for (int ni = 0; ni < 4; ++ni)
            #pragma unroll
            for (int q = 0; q < 4; ++q) acc2[mi][ni][q] = 0.f;
    {
        const int nb = nw * 32;
        const int NC = 40;    // 16 chunks (We2 over H) + 24 chunks (Wer over EH)
        copy_chunk<128, P_B2>(Bs, We2, 0, tid);
        cpa_commit();
        for (int c = 0; c < NC; ++c) {
            if (c + 1 < NC) {
                const float* Wn = (c + 1 < 16) ? We2 : Wer;
                int k0n = (c + 1 < 16) ? (c + 1) * 16 : (c + 1 - 16) * 16;
                copy_chunk<128, P_B2>(Bs + ((c + 1) & 1) * BUFSTRIDE, Wn, k0n, tid);
                cpa_commit();
                cpa_wait1();
            } else {
                cpa_wait0();
            }
            __syncthreads();
            const unsigned* B = (const unsigned*)(Bs + (c & 1) * BUFSTRIDE);
            const float* Ap = (c < 16) ? Hs : As;
            const int pa    = (c < 16) ? P_H : P_A;
            const int kk0   = (c < 16) ? c * 16 : (c - 16) * 16;
            #pragma unroll
            for (int ks = 0; ks < 2; ++ks) {
                int kk = kk0 + ks * 8;
                unsigned a[2][4];
                #pragma unroll
                for (int mi = 0; mi < 2; ++mi) {
                    const unsigned* ap = (const unsigned*)(Ap + (size_t)(mb + mi * 16 + g) * pa + kk + t);
                    a[mi][0] = ap[0];
                    a[mi][1] = ap[8 * pa];
                    a[mi][2] = ap[4];
                    a[mi][3] = ap[8 * pa + 4];
                }
                #pragma unroll
                for (int ni = 0; ni < 4; ++ni) {
                    int col = nb + ni * 8 + g;
                    unsigned b0 = B[(ks * 8 + t) * P_B2 + col];
                    unsigned b1 = B[(ks * 8 + 4 + t) * P_B2 + col];
                    mma8(acc2[0][ni], a[0], b0, b1);
                    mma8(acc2[1][ni], a[1], b0, b1);
                }
            }
            __syncthreads();
        }
    }

    // store O (fp32) into Hs
    {
        const int nb = nw * 32;
        #pragma unroll
        for (int mi = 0; mi < 2; ++mi) {
            int r0 = mb + mi * 16 + g;
            #pragma unroll
            for (int ni = 0; ni < 4; ++ni) {
                int c0 = nb + ni * 8 + 2 * t;
                Hs[(size_t)r0 * P_H + c0]           = acc2[mi][ni][0];
                Hs[(size_t)r0 * P_H + c0 + 1]       = acc2[mi][ni][1];
                Hs[(size_t)(r0 + 8) * P_H + c0]     = acc2[mi][ni][2];
                Hs[(size_t)(r0 + 8) * P_H + c0 + 1] = acc2[mi][ni][3];
            }
        }
    }
    __syncthreads();

    // ---- epilogue: bias + LayerNorm + write + scatter ----
    int c4 = lane * 4;
    float4 g4 = *(const float4*)&ge[c4];
    float4 q4 = *(const float4*)&bge[c4];
    float bo0 = be2[c4 + 0] + ber[c4 + 0];
    float bo1 = be2[c4 + 1] + ber[c4 + 1];
    float bo2 = be2[c4 + 2] + ber[c4 + 2];
    float bo3 = be2[c4 + 3] + ber[c4 + 3];

    #pragma unroll
    for (int i = 0; i < 8; ++i) {
        int m = warp * 8 + i;
        const float* row = Hs + (size_t)m * P_H;
        float v0 = row[c4 + 0] + bo0, v1 = row[c4 + 1] + bo1;
        float v2 = row[c4 + 2] + bo2, v3 = row[c4 + 3] + bo3;
        float s = v0 + v1 + v2 + v3;
        float sq = v0 * v0 + v1 * v1 + v2 * v2 + v3 * v3;
        #pragma unroll
        for (int o = 16; o > 0; o >>= 1) {
            s  += __shfl_xor_sync(0xffffffffu, s, o);
            sq += __shfl_xor_sync(0xffffffffu, sq, o);
        }
        float mu  = s * (1.f / 128.f);
        float var = sq * (1.f / 128.f) - mu * mu;
        float rstd = rsqrtf(var + 1e-5f);
        int e = e0 + m;
        if (e < E) {
            float4 y;
            y.x = (v0 - mu) * rstd * g4.x + q4.x;
            y.y = (v1 - mu) * rstd * g4.y + q4.y;
            y.z = (v2 - mu) * rstd * g4.z + q4.z;
            y.w = (v3 - mu) * rstd * g4.w + q4.w;
            *(float4*)&edge_out[(size_t)e * 128 + c4] = y;
            long long d = clamp_idx(load_idx(ei, (long long)E + e, is64), Nn);
            float* ap = g_agg + (size_t)d * 128 + c4;
            atomicAdd(ap + 0, y.x);
            atomicAdd(ap + 1, y.y);
            atomicAdd(ap + 2, y.z);
            atomicAdd(ap + 3, y.w);
        }
    }
}

// ---------------------------------------------------------------------------
// Node kernel
// ---------------------------------------------------------------------------
__global__ void __launch_bounds__(THREADS, 1)
node_kernel(const float* __restrict__ x,
            const float* __restrict__ bn1, const float* __restrict__ bn2,
            const float* __restrict__ bnr,
            const float* __restrict__ gn,  const float* __restrict__ bgn,
            float* __restrict__ node_out, int Nn)
{
    extern __shared__ float smem[];
    float* As = smem;                   // [64][P_AN]
    float* Hs = As + 64 * P_AN;         // [64][P_H]
    float* Bs = Hs + 64 * P_H;          // [2][BUFSTRIDE]

    const float* Wn1 = g_wtf + OFF_Wn1;
    const float* Wn2 = g_wtf + OFF_Wn2;
    const float* Wnr = g_wtf + OFF_Wnr;

    const int tid  = threadIdx.x;
    const int warp = tid >> 5;
    const int lane = tid & 31;
    const int g    = lane >> 2;
    const int t    = lane & 3;
    const int n0   = blockIdx.x * TILE_M;

    #pragma unroll
    for (int sweep = 0; sweep < 8; ++sweep) {
        int m = sweep * 8 + warp;
        int nn = min(n0 + m, Nn - 1);
        int k = lane * 4;
        float4 v0 = *(const float4*)(x     + (size_t)nn * 128 + k);
        float4 v1 = *(const float4*)(g_agg + (size_t)nn * 128 + k);
        float* row = As + (size_t)m * P_AN;
        *(float4*)(row + k)       = make_float4(f2tf_f(v0.x), f2tf_f(v0.y), f2tf_f(v0.z), f2tf_f(v0.w));
        *(float4*)(row + 128 + k) = make_float4(f2tf_f(v1.x), f2tf_f(v1.y), f2tf_f(v1.z), f2tf_f(v1.w));
    }
    __syncthreads();

    const int mw = warp & 1;
    const int nw = warp >> 1;
    const int mb = mw * 32;

    // GEMM1: H = NH @ Wn1 (64x256, K=256)
    {
        const int nb = nw * 64;
        float acc[2][8][4];
        #pragma unroll
        for (int mi = 0; mi < 2; ++mi)
            #pragma unroll
            for (int ni = 0; ni < 8; ++ni)
                #pragma unroll
                for (int q = 0; q < 4; ++q) acc[mi][ni][q] = 0.f;

        copy_chunk<256, P_B1>(Bs, Wn1, 0, tid);
        cpa_commit();
        for (int kt = 0; kt < 16; ++kt) {
            if (kt + 1 < 16) {
                copy_chunk<256, P_B1>(Bs + ((kt + 1) & 1) * BUFSTRIDE, Wn1, (kt + 1) * 16, tid);
                cpa_commit();
                cpa_wait1();
            } else {
                cpa_wait0();
            }
            __syncthreads();
            const unsigned* B = (const unsigned*)(Bs + (kt & 1) * BUFSTRIDE);
            #pragma unroll
            for (int ks = 0; ks < 2; ++ks) {
                int kk = kt * 16 + ks * 8;
                unsigned a[2][4];
                #pragma unroll
                for (int mi = 0; mi < 2; ++mi) {
                    const unsigned* ap = (const unsigned*)(As + (size_t)(mb + mi * 16 + g) * P_AN + kk + t);
                    a[mi][0] = ap[0];
                    a[mi][1] = ap[8 * P_AN];
                    a[mi][2] = ap[4];
                    a[mi][3] = ap[8 * P_AN + 4];
                }
                #pragma unroll
                for (int ni = 0; ni < 8; ++ni) {
                    int col = nb + ni * 8 + g;
                    unsigned b0 = B[(ks * 8 + t) * P_B1 + col];
                    unsigned b1 = B[(ks * 8 + 4 + t) * P_B1 + col];
                    mma8(acc[0][ni], a[0], b0, b1);
                    mma8(acc[1][ni], a[1], b0, b1);
                }
            }
            __syncthreads();
        }

        #pragma unroll
        for (int mi = 0; mi < 2; ++mi) {
            int r0 = mb + mi * 16 + g;
            #pragma unroll
            for (int ni = 0; ni < 8; ++ni) {
                int c0 = nb + ni * 8 + 2 * t;
                float b0 = __ldg(&bn1[c0]), b1 = __ldg(&bn1[c0 + 1]);
                float v;
                v = acc[mi][ni][0] + b0; Hs[(size_t)r0 * P_H + c0]           = f2tf_f(v / (1.f + __expf(-v)));
                v = acc[mi][ni][1] + b1; Hs[(size_t)r0 * P_H + c0 + 1]       = f2tf_f(v / (1.f + __expf(-v)));
                v = acc[mi][ni][2] + b0; Hs[(size_t)(r0 + 8) * P_H + c0]     = f2tf_f(v / (1.f + __expf(-v)));
                v = acc[mi][ni][3] + b1; Hs[(size_t)(r0 + 8) * P_H + c0 + 1] = f2tf_f(v / (1.f + __expf(-v)));
            }
        }
        __syncthreads();
    }

    // GEMM2: O = H @ Wn2 + NH @ Wnr (64x128, K=256 each)
    float acc2[2][4][4];
    #pragma unroll
    for (int mi = 0; mi < 2; ++mi)
        #pragma unroll
        for (int ni = 0; ni < 4; ++ni)
            #pragma unroll
            for (int q = 0; q < 4; ++q) acc2[mi][ni][q] = 0.f;
    {
        const int nb = nw * 32;
        const int NC = 32;   // 16 (Wn2 over H) + 16 (Wnr over NH)
        copy_chunk<128, P_B2>(Bs, Wn2, 0, tid);
        cpa_commit();
        for (int c = 0; c < NC; ++c) {
            if (c + 1 < NC) {
                const float* Wnx = (c + 1 < 16) ? Wn2 : Wnr;
                int k0n = (c + 1 < 16) ? (c + 1) * 16 : (c + 1 - 16) * 16;
                copy_chunk<128, P_B2>(Bs + ((c + 1) & 1) * BUFSTRIDE, Wnx, k0n, tid);
                cpa_commit();
                cpa_wait1();
            } else {
                cpa_wait0();
            }
            __syncthreads();
            const unsigned* B = (const unsigned*)(Bs + (c & 1) * BUFSTRIDE);
            const float* Ap = (c < 16) ? Hs : As;
            const int pa    = (c < 16) ? P_H : P_AN;
            const int kk0   = (c < 16) ? c * 16 : (c - 16) * 16;
            #pragma unroll
            for (int ks = 0; ks < 2; ++ks) {
                int kk = kk0 + ks * 8;
                unsigned a[2][4];
                #pragma unroll
                for (int mi = 0; mi < 2; ++mi) {
                    const unsigned* ap = (const unsigned*)(Ap + (size_t)(mb + mi * 16 + g) * pa + kk + t);
                    a[mi][0] = ap[0];
                    a[mi][1] = ap[8 * pa];
                    a[mi][2] = ap[4];
                    a[mi][3] = ap[8 * pa + 4];
                }
                #pragma unroll
                for (int ni = 0; ni < 4; ++ni) {
                    int col = nb + ni * 8 + g;
                    unsigned b0 = B[(ks * 8 + t) * P_B2 + col];
                    unsigned b1 = B[(ks * 8 + 4 + t) * P_B2 + col];
                    mma8(acc2[0][ni], a[0], b0, b1);
                    mma8(acc2[1][ni], a[1], b0, b1);
                }
            }
            __syncthreads();
        }
    }

    {
        const int nb = nw * 32;
        #pragma unroll
        for (int mi = 0; mi < 2; ++mi) {
            int r0 = mb + mi * 16 + g;
            #pragma unroll
            for (int ni = 0; ni < 4; ++ni) {
                int c0 = nb + ni * 8 + 2 * t;
                Hs[(size_t)r0 * P_H + c0]           = acc2[mi][ni][0];
                Hs[(size_t)r0 * P_H + c0 + 1]       = acc2[mi][ni][1];
                Hs[(size_t)(r0 + 8) * P_H + c0]     = acc2[mi][ni][2];
                Hs[(size_t)(r0 + 8) * P_H + c0 + 1] = acc2[mi][ni][3];
            }
        }
    }
    __syncthreads();

    int c4 = lane * 4;
    float4 g4 = *(const float4*)&gn[c4];
    float4 q4 = *(const float4*)&bgn[c4];
    float bo0 = bn2[c4 + 0] + bnr[c4 + 0];
    float bo1 = bn2[c4 + 1] + bnr[c4 + 1];
    float bo2 = bn2[c4 + 2] + bnr[c4 + 2];
    float bo3 = bn2[c4 + 3] + bnr[c4 + 3];

    #pragma unroll
    for (int i = 0; i < 8; ++i) {
        int m = warp * 8 + i;
        const float* row = Hs + (size_t)m * P_H;
        float v0 = row[c4 + 0] + bo0, v1 = row[c4 + 1] + bo1;
        float v2 = row[c4 + 2] + bo2, v3 = row[c4 + 3] + bo3;
        float s = v0 + v1 + v2 + v3;
        float sq = v0 * v0 + v1 * v1 + v2 * v2 + v3 * v3;
        #pragma unroll
        for (int o = 16; o > 0; o >>= 1) {
            s  += __shfl_xor_sync(0xffffffffu, s, o);
            sq += __shfl_xor_sync(0xffffffffu, sq, o);
        }
        float mu  = s * (1.f / 128.f);
        float var = sq * (1.f / 128.f) - mu * mu;
        float rstd = rsqrtf(var + 1e-5f);
        int n = n0 + m;
        if (n < Nn) {
            float4 y;
            y.x = (v0 - mu) * rstd * g4.x + q4.x;
            y.y = (v1 - mu) * rstd * g4.y + q4.y;
            y.z = (v2 - mu) * rstd * g4.z + q4.z;
            y.w = (v3 - mu) * rstd * g4.w + q4.w;
            *(float4*)&node_out[(size_t)n * 128 + c4] = y;
        }
    }
}

extern "C" void kernel_launch(void* const* d_in, const int* in_sizes, int n_in,
                              void* d_out, int out_size) {
    const float* x   = (const float*)d_in[0];
    const float* ea  = (const float*)d_in[1];
    const void*  ei  = d_in[2];
    const float* We1 = (const float*)d_in[3];
    const float* be1 = (const float*)d_in[4];
    const float* We2 = (const float*)d_in[5];
    const float* be2 = (const float*)d_in[6];
    const float* Wer = (const float*)d_in[7];
    const float* ber = (const float*)d_in[8];
    const float* ge  = (const float*)d_in[9];
    const float* bge = (const float*)d_in[10];
    const float* Wn1 = (const float*)d_in[11];
    const float* bn1 = (const float*)d_in[12];
    const float* Wn2 = (const float*)d_in[13];
    const float* bn2 = (const float*)d_in[14];
    const float* Wnr = (const float*)d_in[15];
    const float* bnr = (const float*)d_in[16];
    const float* gn  = (const float*)d_in[17];
    const float* bgn = (const float*)d_in[18];

    int Nn = in_sizes[0] / 128;
    int E  = in_sizes[1] / 128;

    float* out      = (float*)d_out;
    float* node_out = out;
    float* edge_out = out + (size_t)Nn * 128;

    cudaFuncSetAttribute(edge_kernel, cudaFuncAttributeMaxDynamicSharedMemorySize,
                         EDGE_SMEM_F * 4);
    cudaFuncSetAttribute(node_kernel, cudaFuncAttributeMaxDynamicSharedMemorySize,
                         NODE_SMEM_F * 4);

    probe_idx_kernel<<<1, 64>>>(ei, E, Nn);
    cvt_weights_kernel<<<(W_TOTAL / 4 + 255) / 256, 256>>>(We1, We2, Wer, Wn1, Wn2, Wnr);

    int nf4 = Nn * 32;
    zero_agg_kernel<<<(nf4 + 255) / 256, 256>>>(nf4);

    edge_kernel<<<(E + TILE_M - 1) / TILE_M, THREADS, EDGE_SMEM_F * 4>>>(
        x, ea, ei, be1, be2, ber, ge, bge, edge_out, E, Nn);

    node_kernel<<<(Nn + TILE_M - 1) / TILE_M, THREADS, NODE_SMEM_F * 4>>>(
        x, bn1, bn2, bnr, gn, bgn, node_out, Nn);
}